// round 6
// baseline (speedup 1.0000x reference)
#include <cuda_runtime.h>
#include <cuda_fp16.h>

// ZINB decoder over 3M edges.
// Stage 1: convert c_feat/g_feat fp32 -> fp16 tables (one 128B line per row).
// Stage 2: persistent gather kernel, 8 threads/edge, 2 edges/group/iteration.
//   Each edge's feature row is ONE warp-wide LDG.128 (8 lanes x 16B = 128B line),
//   halving L1 wavefronts and L2 traffic vs fp32. Products in HMUL2, dots in fp32.

#define BLOCK 256
#define GROUPS_PER_BLOCK (BLOCK / 8)
#define N_CELLS_MAX 50000
#define N_GENES_MAX 20000

__device__ __align__(16) static __half c_half_tbl[N_CELLS_MAX * 64];
__device__ __align__(16) static __half g_half_tbl[N_GENES_MAX * 64];

__device__ __forceinline__ unsigned int h2_as_u32(__half2 h) {
    return *reinterpret_cast<unsigned int*>(&h);
}

// Convert n8 groups of 8 floats -> 8 halves (vectorized: 2x float4 in, uint4 out)
__global__ __launch_bounds__(256)
void cvt_fp16_kernel(const float* __restrict__ src, __half* __restrict__ dst, int n8) {
    int i = blockIdx.x * blockDim.x + threadIdx.x;
    if (i >= n8) return;
    const float4* s = reinterpret_cast<const float4*>(src) + 2 * (size_t)i;
    const float4 a = s[0], b = s[1];
    __half2 h0 = __floats2half2_rn(a.x, a.y);
    __half2 h1 = __floats2half2_rn(a.z, a.w);
    __half2 h2 = __floats2half2_rn(b.x, b.y);
    __half2 h3 = __floats2half2_rn(b.z, b.w);
    uint4 o;
    o.x = h2_as_u32(h0);
    o.y = h2_as_u32(h1);
    o.z = h2_as_u32(h2);
    o.w = h2_as_u32(h3);
    reinterpret_cast<uint4*>(dst)[i] = o;
}

__global__ __launch_bounds__(BLOCK)
void zinb_decoder_kernel(const __half* __restrict__ c_feat,
                         const __half* __restrict__ g_feat,
                         const float* __restrict__ cs_factor,
                         const float* __restrict__ gs_factor,
                         const int*   __restrict__ edge_u,
                         const int*   __restrict__ edge_v,
                         const float* __restrict__ W_mean,
                         const float* __restrict__ b_mean,
                         const float* __restrict__ W_disp,
                         const float* __restrict__ b_disp,
                         const float* __restrict__ W_pi,
                         const float* __restrict__ b_pi,
                         float* __restrict__ out,
                         int n_edges)
{
    const unsigned FULL = 0xffffffffu;
    const int warpLane  = threadIdx.x & 31;
    const int grpInWarp = warpLane >> 3;    // 0..3
    const int lane8     = warpLane & 7;     // 0..7; owns dims lane8*8 .. lane8*8+7

    // ---- weights + biases hoisted to registers (contiguous 8-dim slice) ----
    const float4* wmv = reinterpret_cast<const float4*>(W_mean) + lane8 * 2;
    const float4* wdv = reinterpret_cast<const float4*>(W_disp) + lane8 * 2;
    const float4* wpv = reinterpret_cast<const float4*>(W_pi)   + lane8 * 2;
    const float4 wm0 = __ldg(wmv), wm1 = __ldg(wmv + 1);
    const float4 wd0 = __ldg(wdv), wd1 = __ldg(wdv + 1);
    const float4 wp0 = __ldg(wpv), wp1 = __ldg(wpv + 1);
    const float bm = __ldg(b_mean), bd = __ldg(b_disp), bp = __ldg(b_pi);

    const int warpId = (blockIdx.x * BLOCK + threadIdx.x) >> 5;
    const int stride = gridDim.x * GROUPS_PER_BLOCK;   // total groups

    const bool second  = (warpLane & 4) != 0;          // epilogue lanes 4-7 take set b
    const int  eoLocal = (warpLane & 3);

    for (int ebase = warpId * 4; ebase < n_edges; ebase += 2 * stride) {
        const int e_a = ebase + grpInWarp;
        const int e_b = e_a + stride;
        const bool va = e_a < n_edges;
        const bool vb = e_b < n_edges;

        const int u_a = va ? edge_u[e_a] : 0;
        const int v_a = va ? edge_v[e_a] : 0;
        const int u_b = vb ? edge_u[e_b] : 0;
        const int v_b = vb ? edge_v[e_b] : 0;

        // ---- epilogue-lane scalar gathers, issued early ----
        const int eo  = ebase + eoLocal + (second ? stride : 0);
        const int eoc = eo < n_edges ? eo : 0;
        const float GS = gs_factor[edge_v[eoc]];
        const float CS = cs_factor[edge_u[eoc]];

        // ---- feature gathers: ONE 128B line per row, one LDG.128 per lane ----
        const uint4 cA = reinterpret_cast<const uint4*>(c_feat + (size_t)u_a * 64)[lane8];
        const uint4 gA = reinterpret_cast<const uint4*>(g_feat + (size_t)v_a * 64)[lane8];
        const uint4 cB = reinterpret_cast<const uint4*>(c_feat + (size_t)u_b * 64)[lane8];
        const uint4 gB = reinterpret_cast<const uint4*>(g_feat + (size_t)v_b * 64)[lane8];

        // ---- edge a: h = c*g in fp16 pairs, dot in fp32 ----
        const __half2* ca = reinterpret_cast<const __half2*>(&cA);
        const __half2* ga = reinterpret_cast<const __half2*>(&gA);
        float2 f0 = __half22float2(__hmul2(ca[0], ga[0]));
        float2 f1 = __half22float2(__hmul2(ca[1], ga[1]));
        float2 f2 = __half22float2(__hmul2(ca[2], ga[2]));
        float2 f3 = __half22float2(__hmul2(ca[3], ga[3]));

        float sm_a = f0.x*wm0.x + f0.y*wm0.y + f1.x*wm0.z + f1.y*wm0.w
                   + f2.x*wm1.x + f2.y*wm1.y + f3.x*wm1.z + f3.y*wm1.w;
        float sd_a = f0.x*wd0.x + f0.y*wd0.y + f1.x*wd0.z + f1.y*wd0.w
                   + f2.x*wd1.x + f2.y*wd1.y + f3.x*wd1.z + f3.y*wd1.w;
        float sp_a = f0.x*wp0.x + f0.y*wp0.y + f1.x*wp0.z + f1.y*wp0.w
                   + f2.x*wp1.x + f2.y*wp1.y + f3.x*wp1.z + f3.y*wp1.w;

        // ---- edge b ----
        const __half2* cb = reinterpret_cast<const __half2*>(&cB);
        const __half2* gb = reinterpret_cast<const __half2*>(&gB);
        f0 = __half22float2(__hmul2(cb[0], gb[0]));
        f1 = __half22float2(__hmul2(cb[1], gb[1]));
        f2 = __half22float2(__hmul2(cb[2], gb[2]));
        f3 = __half22float2(__hmul2(cb[3], gb[3]));

        float sm_b = f0.x*wm0.x + f0.y*wm0.y + f1.x*wm0.z + f1.y*wm0.w
                   + f2.x*wm1.x + f2.y*wm1.y + f3.x*wm1.z + f3.y*wm1.w;
        float sd_b = f0.x*wd0.x + f0.y*wd0.y + f1.x*wd0.z + f1.y*wd0.w
                   + f2.x*wd1.x + f2.y*wd1.y + f3.x*wd1.z + f3.y*wd1.w;
        float sp_b = f0.x*wp0.x + f0.y*wp0.y + f1.x*wp0.z + f1.y*wp0.w
                   + f2.x*wp1.x + f2.y*wp1.y + f3.x*wp1.z + f3.y*wp1.w;

        // ---- butterfly reduce within each 8-lane group ----
        #pragma unroll
        for (int off = 4; off > 0; off >>= 1) {
            sm_a += __shfl_xor_sync(FULL, sm_a, off);
            sd_a += __shfl_xor_sync(FULL, sd_a, off);
            sp_a += __shfl_xor_sync(FULL, sp_a, off);
            sm_b += __shfl_xor_sync(FULL, sm_b, off);
            sd_b += __shfl_xor_sync(FULL, sd_b, off);
            sp_b += __shfl_xor_sync(FULL, sp_b, off);
        }

        // ---- distribute the warp's 8 edges to lanes 0-7 ----
        const int srcLane = eoLocal << 3;
        const float SMa = __shfl_sync(FULL, sm_a, srcLane);
        const float SDa = __shfl_sync(FULL, sd_a, srcLane);
        const float SPa = __shfl_sync(FULL, sp_a, srcLane);
        const float SMb = __shfl_sync(FULL, sm_b, srcLane);
        const float SDb = __shfl_sync(FULL, sd_b, srcLane);
        const float SPb = __shfl_sync(FULL, sp_b, srcLane);

        const float SM = second ? SMb : SMa;
        const float SD = second ? SDb : SDa;
        const float SP = second ? SPb : SPa;

        if (warpLane < 8 && eo < n_edges) {
            const float mu_ = 1.0f / (1.0f + expf(-(SM + bm)));
            const float pi  = 1.0f / (1.0f + expf(-(SP + bp)));

            const float x  = GS * (SD + bd);
            const float sx = fmaxf(x, 0.0f) + log1pf(expf(-fabsf(x)));
            const float disp = fminf(fmaxf(sx, 1e-4f), 1e4f);

            const float mu = CS * fminf(fmaxf(expf(GS * mu_) - 1.0f, 1e-5f), 1e6f);

            out[eo]                       = mu;
            out[(size_t)n_edges + eo]     = disp;
            out[(size_t)2 * n_edges + eo] = pi;
        }
    }
}

extern "C" void kernel_launch(void* const* d_in, const int* in_sizes, int n_in,
                              void* d_out, int out_size) {
    const float* c_feat    = (const float*)d_in[0];
    const float* g_feat    = (const float*)d_in[1];
    const float* cs_factor = (const float*)d_in[2];
    const float* gs_factor = (const float*)d_in[3];
    const int*   edge_u    = (const int*)d_in[4];
    const int*   edge_v    = (const int*)d_in[5];
    const float* W_mean    = (const float*)d_in[6];
    const float* b_mean    = (const float*)d_in[7];
    const float* W_disp    = (const float*)d_in[8];
    const float* b_disp    = (const float*)d_in[9];
    const float* W_pi      = (const float*)d_in[10];
    const float* b_pi      = (const float*)d_in[11];

    const int n_edges = in_sizes[4];
    float* out = (float*)d_out;

    __half* c_h = nullptr;
    __half* g_h = nullptr;
    cudaGetSymbolAddress((void**)&c_h, c_half_tbl);
    cudaGetSymbolAddress((void**)&g_h, g_half_tbl);

    // Stage 1: fp32 -> fp16 table conversion (same stream -> ordered before stage 2)
    const int c_n8 = in_sizes[0] / 8;
    const int g_n8 = in_sizes[1] / 8;
    cvt_fp16_kernel<<<(c_n8 + 255) / 256, 256>>>(c_feat, c_h, c_n8);
    cvt_fp16_kernel<<<(g_n8 + 255) / 256, 256>>>(g_feat, g_h, g_n8);

    // Stage 2: main decoder
    const int blocks = 1184;  // 148 SMs * 8
    zinb_decoder_kernel<<<blocks, BLOCK>>>(
        c_h, g_h, cs_factor, gs_factor, edge_u, edge_v,
        W_mean, b_mean, W_disp, b_disp, W_pi, b_pi,
        out, n_edges);
}

// round 7
// speedup vs baseline: 1.2901x; 1.2901x over previous
#include <cuda_runtime.h>
#include <cuda_fp16.h>

// ZINB decoder over 3M edges.
// Stage 1: fp32 -> fp16 feature tables (row = 64 halves = one 128B line).
// Stage 2: persistent kernel; each warp processes 16 CONSECUTIVE edges per
//   iteration as 4 "sets" x 4 groups (8 lanes/edge). Dots via packed f32x2 FMA,
//   cross-lane reduction via reduce-scatter (12 SHFL/16 edges), epilogue runs
//   on 16 lanes in parallel with fast-math intrinsics, stores fully coalesced.

#define BLOCK 256
#define N_CELLS_MAX 50000
#define N_GENES_MAX 20000

__device__ __align__(16) static __half c_half_tbl[N_CELLS_MAX * 64];
__device__ __align__(16) static __half g_half_tbl[N_GENES_MAX * 64];

typedef unsigned long long u64;

__device__ __forceinline__ u64 pack2(float x, float y) {
    u64 r; asm("mov.b64 %0, {%1,%2};" : "=l"(r) : "f"(x), "f"(y)); return r;
}
__device__ __forceinline__ u64 fma2(u64 a, u64 b, u64 c) {
    u64 d; asm("fma.rn.f32x2 %0, %1, %2, %3;" : "=l"(d) : "l"(a), "l"(b), "l"(c)); return d;
}
__device__ __forceinline__ float unpack_sum(u64 v) {
    float lo, hi; asm("mov.b64 {%0,%1}, %2;" : "=f"(lo), "=f"(hi) : "l"(v));
    return lo + hi;
}
__device__ __forceinline__ unsigned int h2_as_u32(__half2 h) {
    return *reinterpret_cast<unsigned int*>(&h);
}

// fp32 -> fp16 conversion (8 floats per thread)
__global__ __launch_bounds__(256)
void cvt_fp16_kernel(const float* __restrict__ src, __half* __restrict__ dst, int n8) {
    int i = blockIdx.x * blockDim.x + threadIdx.x;
    if (i >= n8) return;
    const float4* s = reinterpret_cast<const float4*>(src) + 2 * (size_t)i;
    const float4 a = s[0], b = s[1];
    uint4 o;
    o.x = h2_as_u32(__floats2half2_rn(a.x, a.y));
    o.y = h2_as_u32(__floats2half2_rn(a.z, a.w));
    o.z = h2_as_u32(__floats2half2_rn(b.x, b.y));
    o.w = h2_as_u32(__floats2half2_rn(b.z, b.w));
    reinterpret_cast<uint4*>(dst)[i] = o;
}

__global__ __launch_bounds__(BLOCK)
void zinb_decoder_kernel(const __half* __restrict__ c_feat,
                         const __half* __restrict__ g_feat,
                         const float* __restrict__ cs_factor,
                         const float* __restrict__ gs_factor,
                         const int*   __restrict__ edge_u,
                         const int*   __restrict__ edge_v,
                         const float* __restrict__ W_mean,
                         const float* __restrict__ b_mean,
                         const float* __restrict__ W_disp,
                         const float* __restrict__ b_disp,
                         const float* __restrict__ W_pi,
                         const float* __restrict__ b_pi,
                         float* __restrict__ out,
                         int n_edges)
{
    const unsigned FULL = 0xffffffffu;
    const int warpLane = threadIdx.x & 31;
    const int grp      = warpLane >> 3;    // 0..3
    const int lane8    = warpLane & 7;     // owns dims lane8*8 .. lane8*8+7

    // epilogue set id for this lane: s = 2*bit2 + bit1 (same for lane pairs {2k,2k+1})
    const int sl = ((warpLane & 4) >> 1) | ((warpLane & 2) >> 1);

    // ---- weights packed as f32x2, biases (registers, loaded once) ----
    const float4* wmv = reinterpret_cast<const float4*>(W_mean) + lane8 * 2;
    const float4* wdv = reinterpret_cast<const float4*>(W_disp) + lane8 * 2;
    const float4* wpv = reinterpret_cast<const float4*>(W_pi)   + lane8 * 2;
    const float4 a0 = __ldg(wmv), a1 = __ldg(wmv + 1);
    const float4 d0 = __ldg(wdv), d1 = __ldg(wdv + 1);
    const float4 p0 = __ldg(wpv), p1 = __ldg(wpv + 1);
    const u64 wm0 = pack2(a0.x, a0.y), wm1 = pack2(a0.z, a0.w),
              wm2 = pack2(a1.x, a1.y), wm3 = pack2(a1.z, a1.w);
    const u64 wd0 = pack2(d0.x, d0.y), wd1 = pack2(d0.z, d0.w),
              wd2 = pack2(d1.x, d1.y), wd3 = pack2(d1.z, d1.w);
    const u64 wp0 = pack2(p0.x, p0.y), wp1 = pack2(p0.z, p0.w),
              wp2 = pack2(p1.x, p1.y), wp3 = pack2(p1.z, p1.w);
    const float bm = __ldg(b_mean), bd = __ldg(b_disp), bp = __ldg(b_pi);

    const int warpId  = (blockIdx.x * BLOCK + threadIdx.x) >> 5;
    const int nWarps  = gridDim.x * (BLOCK >> 5);
    const int tileStr = nWarps * 16;

    const uint4* ctab = reinterpret_cast<const uint4*>(c_feat);
    const uint4* gtab = reinterpret_cast<const uint4*>(g_feat);

    for (int ebase = warpId * 16; ebase < n_edges; ebase += tileStr) {
        // set s, group grp -> edge ebase + 4s + grp
        int e0 = ebase + grp;
        int ec0 = e0      < n_edges ? e0      : 0;
        int ec1 = e0 + 4  < n_edges ? e0 + 4  : 0;
        int ec2 = e0 + 8  < n_edges ? e0 + 8  : 0;
        int ec3 = e0 + 12 < n_edges ? e0 + 12 : 0;

        const int u0 = edge_u[ec0], v0 = edge_v[ec0];
        const int u1 = edge_u[ec1], v1 = edge_v[ec1];
        const int u2 = edge_u[ec2], v2 = edge_v[ec2];
        const int u3 = edge_u[ec3], v3 = edge_v[ec3];

        // ---- epilogue-lane scalar gathers (select own set, issue early) ----
        const int uSel = sl < 2 ? (sl == 0 ? u0 : u1) : (sl == 2 ? u2 : u3);
        const int vSel = sl < 2 ? (sl == 0 ? v0 : v1) : (sl == 2 ? v2 : v3);
        const float GS = gs_factor[vSel];
        const float CS = cs_factor[uSel];

        // ---- feature gathers: 8 x LDG.128, each row = one 128B line ----
        const uint4 C0 = ctab[(size_t)u0 * 8 + lane8];
        const uint4 G0 = gtab[(size_t)v0 * 8 + lane8];
        const uint4 C1 = ctab[(size_t)u1 * 8 + lane8];
        const uint4 G1 = gtab[(size_t)v1 * 8 + lane8];
        const uint4 C2 = ctab[(size_t)u2 * 8 + lane8];
        const uint4 G2 = gtab[(size_t)v2 * 8 + lane8];
        const uint4 C3 = ctab[(size_t)u3 * 8 + lane8];
        const uint4 G3 = gtab[(size_t)v3 * 8 + lane8];

        float m[4], d[4], p[4];
        #pragma unroll
        for (int s = 0; s < 4; s++) {
            const uint4& C = s == 0 ? C0 : s == 1 ? C1 : s == 2 ? C2 : C3;
            const uint4& G = s == 0 ? G0 : s == 1 ? G1 : s == 2 ? G2 : G3;
            const __half2* ch = reinterpret_cast<const __half2*>(&C);
            const __half2* gh = reinterpret_cast<const __half2*>(&G);
            const float2 q0 = __half22float2(__hmul2(ch[0], gh[0]));
            const float2 q1 = __half22float2(__hmul2(ch[1], gh[1]));
            const float2 q2 = __half22float2(__hmul2(ch[2], gh[2]));
            const float2 q3 = __half22float2(__hmul2(ch[3], gh[3]));
            const u64 h0 = pack2(q0.x, q0.y), h1 = pack2(q1.x, q1.y);
            const u64 h2 = pack2(q2.x, q2.y), h3 = pack2(q3.x, q3.y);
            u64 am = fma2(h0, wm0, fma2(h1, wm1, fma2(h2, wm2, fma2(h3, wm3, 0ull))));
            u64 ad = fma2(h0, wd0, fma2(h1, wd1, fma2(h2, wd2, fma2(h3, wd3, 0ull))));
            u64 ap = fma2(h0, wp0, fma2(h1, wp1, fma2(h2, wp2, fma2(h3, wp3, 0ull))));
            m[s] = unpack_sum(am);
            d[s] = unpack_sum(ad);
            p[s] = unpack_sum(ap);
        }

        // ---- reduce-scatter across 8 lanes: 12 SHFL total ----
        // step 1 (xor 4): keep pair {2*b2, 2*b2+1}; A = set 2*b2, B = set 2*b2+1
        const bool hi4 = (warpLane & 4) != 0;
        float Am = hi4 ? m[2] : m[0], Ad = hi4 ? d[2] : d[0], Ap = hi4 ? p[2] : p[0];
        float Bm = hi4 ? m[3] : m[1], Bd = hi4 ? d[3] : d[1], Bp = hi4 ? p[3] : p[1];
        Am += __shfl_xor_sync(FULL, hi4 ? m[0] : m[2], 4);
        Ad += __shfl_xor_sync(FULL, hi4 ? d[0] : d[2], 4);
        Ap += __shfl_xor_sync(FULL, hi4 ? p[0] : p[2], 4);
        Bm += __shfl_xor_sync(FULL, hi4 ? m[1] : m[3], 4);
        Bd += __shfl_xor_sync(FULL, hi4 ? d[1] : d[3], 4);
        Bp += __shfl_xor_sync(FULL, hi4 ? p[1] : p[3], 4);
        // step 2 (xor 2): keep (b1 ? B : A) -> set s = 2*b2 + b1
        const bool hi2 = (warpLane & 2) != 0;
        float Rm = hi2 ? Bm : Am, Rd = hi2 ? Bd : Ad, Rp = hi2 ? Bp : Ap;
        Rm += __shfl_xor_sync(FULL, hi2 ? Am : Bm, 2);
        Rd += __shfl_xor_sync(FULL, hi2 ? Ad : Bd, 2);
        Rp += __shfl_xor_sync(FULL, hi2 ? Ap : Bp, 2);
        // step 3 (xor 1): full sum on both lanes of the pair
        Rm += __shfl_xor_sync(FULL, Rm, 1);
        Rd += __shfl_xor_sync(FULL, Rd, 1);
        Rp += __shfl_xor_sync(FULL, Rp, 1);

        // ---- epilogue: 16 lanes (even lanes), one edge each ----
        const int eo = ebase + 4 * sl + grp;
        if ((warpLane & 1) == 0 && eo < n_edges) {
            const float mu_ = __fdividef(1.0f, 1.0f + __expf(-(Rm + bm)));
            const float pi  = __fdividef(1.0f, 1.0f + __expf(-(Rp + bp)));

            const float x  = GS * (Rd + bd);
            const float sx = fmaxf(x, 0.0f) + __logf(1.0f + __expf(-fabsf(x)));
            const float disp = fminf(fmaxf(sx, 1e-4f), 1e4f);

            const float mu = CS * fminf(fmaxf(__expf(GS * mu_) - 1.0f, 1e-5f), 1e6f);

            out[eo]                       = mu;
            out[(size_t)n_edges + eo]     = disp;
            out[(size_t)2 * n_edges + eo] = pi;
        }
    }
}

extern "C" void kernel_launch(void* const* d_in, const int* in_sizes, int n_in,
                              void* d_out, int out_size) {
    const float* c_feat    = (const float*)d_in[0];
    const float* g_feat    = (const float*)d_in[1];
    const float* cs_factor = (const float*)d_in[2];
    const float* gs_factor = (const float*)d_in[3];
    const int*   edge_u    = (const int*)d_in[4];
    const int*   edge_v    = (const int*)d_in[5];
    const float* W_mean    = (const float*)d_in[6];
    const float* b_mean    = (const float*)d_in[7];
    const float* W_disp    = (const float*)d_in[8];
    const float* b_disp    = (const float*)d_in[9];
    const float* W_pi      = (const float*)d_in[10];
    const float* b_pi      = (const float*)d_in[11];

    const int n_edges = in_sizes[4];
    float* out = (float*)d_out;

    __half* c_h = nullptr;
    __half* g_h = nullptr;
    cudaGetSymbolAddress((void**)&c_h, c_half_tbl);
    cudaGetSymbolAddress((void**)&g_h, g_half_tbl);

    const int c_n8 = in_sizes[0] / 8;
    const int g_n8 = in_sizes[1] / 8;
    cvt_fp16_kernel<<<(c_n8 + 255) / 256, 256>>>(c_feat, c_h, c_n8);
    cvt_fp16_kernel<<<(g_n8 + 255) / 256, 256>>>(g_feat, g_h, g_n8);

    const int blocks = 1184;  // 148 SMs * 8
    zinb_decoder_kernel<<<blocks, BLOCK>>>(
        c_h, g_h, cs_factor, gs_factor, edge_u, edge_v,
        W_mean, b_mean, W_disp, b_disp, W_pi, b_pi,
        out, n_edges);
}

// round 8
// speedup vs baseline: 1.5420x; 1.1952x over previous
#include <cuda_runtime.h>
#include <cuda_fp16.h>

// ZINB decoder over 3M edges.
// Stage 1 (single launch): fp32 -> fp16 feature tables (row = one 128B line).
// Stage 2: persistent kernel; each warp = 16 consecutive edges per iteration,
//   4 sets x 4 groups (8 lanes/edge). f32x2 packed FMA dots, reduce-scatter
//   (12 SHFL/16 edges), 16-lane fast-math epilogue, coalesced stores.
//   Index loads for tile t+1 are PREFETCHED during tile t's compute, removing
//   one dependent L2 round-trip from the per-iteration critical path.

#define BLOCK 256
#define N_CELLS_MAX 50000
#define N_GENES_MAX 20000

__device__ __align__(16) static __half c_half_tbl[N_CELLS_MAX * 64];
__device__ __align__(16) static __half g_half_tbl[N_GENES_MAX * 64];

typedef unsigned long long u64;

__device__ __forceinline__ u64 pack2(float x, float y) {
    u64 r; asm("mov.b64 %0, {%1,%2};" : "=l"(r) : "f"(x), "f"(y)); return r;
}
__device__ __forceinline__ u64 fma2(u64 a, u64 b, u64 c) {
    u64 d; asm("fma.rn.f32x2 %0, %1, %2, %3;" : "=l"(d) : "l"(a), "l"(b), "l"(c)); return d;
}
__device__ __forceinline__ float unpack_sum(u64 v) {
    float lo, hi; asm("mov.b64 {%0,%1}, %2;" : "=f"(lo), "=f"(hi) : "l"(v));
    return lo + hi;
}
__device__ __forceinline__ unsigned int h2_as_u32(__half2 h) {
    return *reinterpret_cast<unsigned int*>(&h);
}

// Fused fp32 -> fp16 conversion for both tables (8 floats per thread).
__global__ __launch_bounds__(256)
void cvt_fp16_kernel(const float* __restrict__ srcA, __half* __restrict__ dstA, int nA8,
                     const float* __restrict__ srcB, __half* __restrict__ dstB, int nB8) {
    int i = blockIdx.x * blockDim.x + threadIdx.x;
    const float* src; __half* dst; int j;
    if (i < nA8) { src = srcA; dst = dstA; j = i; }
    else if (i < nA8 + nB8) { src = srcB; dst = dstB; j = i - nA8; }
    else return;
    const float4* s = reinterpret_cast<const float4*>(src) + 2 * (size_t)j;
    const float4 a = s[0], b = s[1];
    uint4 o;
    o.x = h2_as_u32(__floats2half2_rn(a.x, a.y));
    o.y = h2_as_u32(__floats2half2_rn(a.z, a.w));
    o.z = h2_as_u32(__floats2half2_rn(b.x, b.y));
    o.w = h2_as_u32(__floats2half2_rn(b.z, b.w));
    reinterpret_cast<uint4*>(dst)[j] = o;
}

__global__ __launch_bounds__(BLOCK)
void zinb_decoder_kernel(const __half* __restrict__ c_feat,
                         const __half* __restrict__ g_feat,
                         const float* __restrict__ cs_factor,
                         const float* __restrict__ gs_factor,
                         const int*   __restrict__ edge_u,
                         const int*   __restrict__ edge_v,
                         const float* __restrict__ W_mean,
                         const float* __restrict__ b_mean,
                         const float* __restrict__ W_disp,
                         const float* __restrict__ b_disp,
                         const float* __restrict__ W_pi,
                         const float* __restrict__ b_pi,
                         float* __restrict__ out,
                         int n_edges)
{
    const unsigned FULL = 0xffffffffu;
    const int warpLane = threadIdx.x & 31;
    const int grp      = warpLane >> 3;    // 0..3
    const int lane8    = warpLane & 7;     // owns dims lane8*8 .. lane8*8+7

    // epilogue set id for this lane: s = 2*bit2 + bit1 (same for lane pairs {2k,2k+1})
    const int sl = ((warpLane & 4) >> 1) | ((warpLane & 2) >> 1);

    // ---- weights packed as f32x2, biases (registers, loaded once) ----
    const float4* wmv = reinterpret_cast<const float4*>(W_mean) + lane8 * 2;
    const float4* wdv = reinterpret_cast<const float4*>(W_disp) + lane8 * 2;
    const float4* wpv = reinterpret_cast<const float4*>(W_pi)   + lane8 * 2;
    const float4 a0 = __ldg(wmv), a1 = __ldg(wmv + 1);
    const float4 d0 = __ldg(wdv), d1 = __ldg(wdv + 1);
    const float4 p0 = __ldg(wpv), p1 = __ldg(wpv + 1);
    const u64 wm0 = pack2(a0.x, a0.y), wm1 = pack2(a0.z, a0.w),
              wm2 = pack2(a1.x, a1.y), wm3 = pack2(a1.z, a1.w);
    const u64 wd0 = pack2(d0.x, d0.y), wd1 = pack2(d0.z, d0.w),
              wd2 = pack2(d1.x, d1.y), wd3 = pack2(d1.z, d1.w);
    const u64 wp0 = pack2(p0.x, p0.y), wp1 = pack2(p0.z, p0.w),
              wp2 = pack2(p1.x, p1.y), wp3 = pack2(p1.z, p1.w);
    const float bm = __ldg(b_mean), bd = __ldg(b_disp), bp = __ldg(b_pi);

    const int warpId  = (blockIdx.x * BLOCK + threadIdx.x) >> 5;
    const int nWarps  = gridDim.x * (BLOCK >> 5);
    const int tileStr = nWarps * 16;

    const uint4* ctab = reinterpret_cast<const uint4*>(c_feat);
    const uint4* gtab = reinterpret_cast<const uint4*>(g_feat);

    int ebase = warpId * 16;
    if (ebase >= n_edges) return;

    // ---- prime the index pipeline for the first tile ----
    int u0, v0, u1, v1, u2, v2, u3, v3;
    {
        const int e0 = ebase + grp;
        const int ec0 = e0      < n_edges ? e0      : 0;
        const int ec1 = e0 + 4  < n_edges ? e0 + 4  : 0;
        const int ec2 = e0 + 8  < n_edges ? e0 + 8  : 0;
        const int ec3 = e0 + 12 < n_edges ? e0 + 12 : 0;
        u0 = edge_u[ec0]; v0 = edge_v[ec0];
        u1 = edge_u[ec1]; v1 = edge_v[ec1];
        u2 = edge_u[ec2]; v2 = edge_v[ec2];
        u3 = edge_u[ec3]; v3 = edge_v[ec3];
    }

    for (; ebase < n_edges; ebase += tileStr) {
        // ---- feature gathers for CURRENT tile (indices already resident) ----
        const uint4 C0 = ctab[(size_t)u0 * 8 + lane8];
        const uint4 G0 = gtab[(size_t)v0 * 8 + lane8];
        const uint4 C1 = ctab[(size_t)u1 * 8 + lane8];
        const uint4 G1 = gtab[(size_t)v1 * 8 + lane8];
        const uint4 C2 = ctab[(size_t)u2 * 8 + lane8];
        const uint4 G2 = gtab[(size_t)v2 * 8 + lane8];
        const uint4 C3 = ctab[(size_t)u3 * 8 + lane8];
        const uint4 G3 = gtab[(size_t)v3 * 8 + lane8];

        // ---- epilogue-lane scalar gathers (current tile, issue early) ----
        const int uSel = sl < 2 ? (sl == 0 ? u0 : u1) : (sl == 2 ? u2 : u3);
        const int vSel = sl < 2 ? (sl == 0 ? v0 : v1) : (sl == 2 ? v2 : v3);
        const float GS = gs_factor[vSel];
        const float CS = cs_factor[uSel];

        // ---- PREFETCH indices for NEXT tile (overlaps with compute below) ----
        int nu0, nv0, nu1, nv1, nu2, nv2, nu3, nv3;
        {
            const int nb = ebase + tileStr;
            const int e0 = nb + grp;
            const int ec0 = e0      < n_edges ? e0      : 0;
            const int ec1 = e0 + 4  < n_edges ? e0 + 4  : 0;
            const int ec2 = e0 + 8  < n_edges ? e0 + 8  : 0;
            const int ec3 = e0 + 12 < n_edges ? e0 + 12 : 0;
            nu0 = edge_u[ec0]; nv0 = edge_v[ec0];
            nu1 = edge_u[ec1]; nv1 = edge_v[ec1];
            nu2 = edge_u[ec2]; nv2 = edge_v[ec2];
            nu3 = edge_u[ec3]; nv3 = edge_v[ec3];
        }

        float m[4], d[4], p[4];
        #pragma unroll
        for (int s = 0; s < 4; s++) {
            const uint4& C = s == 0 ? C0 : s == 1 ? C1 : s == 2 ? C2 : C3;
            const uint4& G = s == 0 ? G0 : s == 1 ? G1 : s == 2 ? G2 : G3;
            const __half2* ch = reinterpret_cast<const __half2*>(&C);
            const __half2* gh = reinterpret_cast<const __half2*>(&G);
            const float2 q0 = __half22float2(__hmul2(ch[0], gh[0]));
            const float2 q1 = __half22float2(__hmul2(ch[1], gh[1]));
            const float2 q2 = __half22float2(__hmul2(ch[2], gh[2]));
            const float2 q3 = __half22float2(__hmul2(ch[3], gh[3]));
            const u64 h0 = pack2(q0.x, q0.y), h1 = pack2(q1.x, q1.y);
            const u64 h2 = pack2(q2.x, q2.y), h3 = pack2(q3.x, q3.y);
            u64 am = fma2(h0, wm0, fma2(h1, wm1, fma2(h2, wm2, fma2(h3, wm3, 0ull))));
            u64 ad = fma2(h0, wd0, fma2(h1, wd1, fma2(h2, wd2, fma2(h3, wd3, 0ull))));
            u64 ap = fma2(h0, wp0, fma2(h1, wp1, fma2(h2, wp2, fma2(h3, wp3, 0ull))));
            m[s] = unpack_sum(am);
            d[s] = unpack_sum(ad);
            p[s] = unpack_sum(ap);
        }

        // ---- reduce-scatter across 8 lanes: 12 SHFL total ----
        const bool hi4 = (warpLane & 4) != 0;
        float Am = hi4 ? m[2] : m[0], Ad = hi4 ? d[2] : d[0], Ap = hi4 ? p[2] : p[0];
        float Bm = hi4 ? m[3] : m[1], Bd = hi4 ? d[3] : d[1], Bp = hi4 ? p[3] : p[1];
        Am += __shfl_xor_sync(FULL, hi4 ? m[0] : m[2], 4);
        Ad += __shfl_xor_sync(FULL, hi4 ? d[0] : d[2], 4);
        Ap += __shfl_xor_sync(FULL, hi4 ? p[0] : p[2], 4);
        Bm += __shfl_xor_sync(FULL, hi4 ? m[1] : m[3], 4);
        Bd += __shfl_xor_sync(FULL, hi4 ? d[1] : d[3], 4);
        Bp += __shfl_xor_sync(FULL, hi4 ? p[1] : p[3], 4);
        const bool hi2 = (warpLane & 2) != 0;
        float Rm = hi2 ? Bm : Am, Rd = hi2 ? Bd : Ad, Rp = hi2 ? Bp : Ap;
        Rm += __shfl_xor_sync(FULL, hi2 ? Am : Bm, 2);
        Rd += __shfl_xor_sync(FULL, hi2 ? Ad : Bd, 2);
        Rp += __shfl_xor_sync(FULL, hi2 ? Ap : Bp, 2);
        Rm += __shfl_xor_sync(FULL, Rm, 1);
        Rd += __shfl_xor_sync(FULL, Rd, 1);
        Rp += __shfl_xor_sync(FULL, Rp, 1);

        // ---- epilogue: 16 even lanes, one edge each ----
        const int eo = ebase + 4 * sl + grp;
        if ((warpLane & 1) == 0 && eo < n_edges) {
            const float mu_ = __fdividef(1.0f, 1.0f + __expf(-(Rm + bm)));
            const float pi  = __fdividef(1.0f, 1.0f + __expf(-(Rp + bp)));

            const float x  = GS * (Rd + bd);
            const float sx = fmaxf(x, 0.0f) + __logf(1.0f + __expf(-fabsf(x)));
            const float disp = fminf(fmaxf(sx, 1e-4f), 1e4f);

            const float mu = CS * fminf(fmaxf(__expf(GS * mu_) - 1.0f, 1e-5f), 1e6f);

            out[eo]                       = mu;
            out[(size_t)n_edges + eo]     = disp;
            out[(size_t)2 * n_edges + eo] = pi;
        }

        // ---- rotate prefetched indices in ----
        u0 = nu0; v0 = nv0; u1 = nu1; v1 = nv1;
        u2 = nu2; v2 = nv2; u3 = nu3; v3 = nv3;
    }
}

extern "C" void kernel_launch(void* const* d_in, const int* in_sizes, int n_in,
                              void* d_out, int out_size) {
    const float* c_feat    = (const float*)d_in[0];
    const float* g_feat    = (const float*)d_in[1];
    const float* cs_factor = (const float*)d_in[2];
    const float* gs_factor = (const float*)d_in[3];
    const int*   edge_u    = (const int*)d_in[4];
    const int*   edge_v    = (const int*)d_in[5];
    const float* W_mean    = (const float*)d_in[6];
    const float* b_mean    = (const float*)d_in[7];
    const float* W_disp    = (const float*)d_in[8];
    const float* b_disp    = (const float*)d_in[9];
    const float* W_pi      = (const float*)d_in[10];
    const float* b_pi      = (const float*)d_in[11];

    const int n_edges = in_sizes[4];
    float* out = (float*)d_out;

    __half* c_h = nullptr;
    __half* g_h = nullptr;
    cudaGetSymbolAddress((void**)&c_h, c_half_tbl);
    cudaGetSymbolAddress((void**)&g_h, g_half_tbl);

    const int c_n8 = in_sizes[0] / 8;
    const int g_n8 = in_sizes[1] / 8;
    const int cvt_threads = c_n8 + g_n8;
    cvt_fp16_kernel<<<(cvt_threads + 255) / 256, 256>>>(c_feat, c_h, c_n8,
                                                        g_feat, g_h, g_n8);

    const int blocks = 1184;  // 148 SMs * 8
    zinb_decoder_kernel<<<blocks, BLOCK>>>(
        c_h, g_h, cs_factor, gs_factor, edge_u, edge_v,
        W_mean, b_mean, W_disp, b_disp, W_pi, b_pi,
        out, n_edges);
}